// round 3
// baseline (speedup 1.0000x reference)
#include <cuda_runtime.h>
#include <math.h>
#include <stdint.h>

// Problem constants (dataset-fixed): B=2, d_model=1024, SPLIT=64.
// n_avail derived from in_sizes[0] at launch.
#define BATCH   2
#define DMODEL  1024
#define SPLIT   64
#define KTOP    7

// Scratch (device globals; no allocation allowed)
__device__ float g_invncur[BATCH * SPLIT];      // inverse norms of current split rows
__device__ float g_scores[BATCH * 2048];        // scores[b][n]

// ---------------------------------------------------------------------------
// Kernel A: inverse L2 norms of the current split's 64 rows per batch.
// grid (SPLIT, BATCH), 128 threads.
// ---------------------------------------------------------------------------
__global__ void curnorm_kernel(const float* __restrict__ emb, int csi) {
    int q = blockIdx.x;
    int b = blockIdx.y;
    const float* row = emb + ((size_t)(b * (csi + 1) + csi) * SPLIT + q) * DMODEL;
    int tid = threadIdx.x;

    float ss = 0.f;
    // 1024 floats = 256 float4; 128 threads x 2
    #pragma unroll
    for (int it = 0; it < 2; it++) {
        float4 v = *(const float4*)(row + (tid + it * 128) * 4);
        ss += v.x * v.x + v.y * v.y + v.z * v.z + v.w * v.w;
    }
    // warp reduce
    #pragma unroll
    for (int o = 16; o > 0; o >>= 1)
        ss += __shfl_xor_sync(0xFFFFFFFF, ss, o);
    __shared__ float wred[4];
    if ((tid & 31) == 0) wred[tid >> 5] = ss;
    __syncthreads();
    if (tid == 0) {
        float t = wred[0] + wred[1] + wred[2] + wred[3];
        g_invncur[b * SPLIT + q] = 1.0f / fmaxf(sqrtf(t), 1e-12f);
    }
}

// ---------------------------------------------------------------------------
// Kernel B: per (b, n): 64x64x1024 dot matrix of cur x prev_n^T, fused
// prev-row norms, row-max over p, weighted sum over q -> scores[b][n].
// grid (csi, BATCH), 256 threads (16x16), 4x4 register tile, K-chunk 64.
// SMEM tiles stored transposed [k][row] with pad 68 to kill bank conflicts.
// ---------------------------------------------------------------------------
__global__ void __launch_bounds__(256) sim_kernel(const float* __restrict__ emb, int csi) {
    int n = blockIdx.x;
    int b = blockIdx.y;

    const float* cur  = emb + ((size_t)b * (csi + 1) + csi) * SPLIT * DMODEL;
    const float* prev = emb + ((size_t)b * (csi + 1) + n)   * SPLIT * DMODEL;

    __shared__ __align__(16) float As[64][68];   // As[k][q]  (cur, transposed)
    __shared__ __align__(16) float Bs[64][68];   // Bs[k][p]  (prev, transposed)

    int tid = threadIdx.x;
    int tx = tid & 15;          // p tile
    int ty = tid >> 4;          // q tile
    int prow  = tid & 63;       // sumsq row
    int kpart = tid >> 6;       // sumsq k-quarter

    float acc[4][4];
    #pragma unroll
    for (int i = 0; i < 4; i++)
        #pragma unroll
        for (int j = 0; j < 4; j++) acc[i][j] = 0.f;
    float ssq = 0.f;

    for (int kk = 0; kk < DMODEL; kk += 64) {
        // Load 64 rows x 64 cols of each operand, transposed into SMEM.
        #pragma unroll
        for (int it = 0; it < 4; it++) {
            int lin = tid + it * 256;   // 0..1023
            int c4  = lin & 15;         // float4 column index
            int row = lin >> 4;         // 0..63
            float4 va = *(const float4*)(cur  + (size_t)row * DMODEL + kk + c4 * 4);
            float4 vb = *(const float4*)(prev + (size_t)row * DMODEL + kk + c4 * 4);
            As[c4 * 4 + 0][row] = va.x; As[c4 * 4 + 1][row] = va.y;
            As[c4 * 4 + 2][row] = va.z; As[c4 * 4 + 3][row] = va.w;
            Bs[c4 * 4 + 0][row] = vb.x; Bs[c4 * 4 + 1][row] = vb.y;
            Bs[c4 * 4 + 2][row] = vb.z; Bs[c4 * 4 + 3][row] = vb.w;
        }
        __syncthreads();

        // Fused prev-row sumsq: thread covers (row = prow, k quarter = kpart).
        #pragma unroll
        for (int k2 = 0; k2 < 16; k2++) {
            float v = Bs[kpart * 16 + k2][prow];
            ssq += v * v;
        }

        // Main 4x4 outer-product accumulation.
        #pragma unroll
        for (int k = 0; k < 64; k++) {
            float4 a  = *(const float4*)&As[k][ty * 4];
            float4 b4 = *(const float4*)&Bs[k][tx * 4];
            acc[0][0] += a.x * b4.x; acc[0][1] += a.x * b4.y; acc[0][2] += a.x * b4.z; acc[0][3] += a.x * b4.w;
            acc[1][0] += a.y * b4.x; acc[1][1] += a.y * b4.y; acc[1][2] += a.y * b4.z; acc[1][3] += a.y * b4.w;
            acc[2][0] += a.z * b4.x; acc[2][1] += a.z * b4.y; acc[2][2] += a.z * b4.z; acc[2][3] += a.z * b4.w;
            acc[3][0] += a.w * b4.x; acc[3][1] += a.w * b4.y; acc[3][2] += a.w * b4.z; acc[3][3] += a.w * b4.w;
        }
        __syncthreads();
    }

    // Reduce prev sumsq -> inverse norms.
    __shared__ float sred[4][64];
    sred[kpart][prow] = ssq;
    __syncthreads();
    __shared__ float sinvp[64];
    if (tid < 64) {
        float t = sred[0][tid] + sred[1][tid] + sred[2][tid] + sred[3][tid];
        sinvp[tid] = 1.0f / fmaxf(sqrtf(t), 1e-12f);
    }
    __syncthreads();

    // Per-thread max over its 4 p's (after scaling by invp), then reduce over tx.
    __shared__ float smax[64][17];
    #pragma unroll
    for (int i = 0; i < 4; i++) {
        float m = -INFINITY;
        #pragma unroll
        for (int j = 0; j < 4; j++)
            m = fmaxf(m, acc[i][j] * sinvp[tx * 4 + j]);
        smax[ty * 4 + i][tx] = m;
    }
    __syncthreads();

    __shared__ float scol[64];
    if (tid < 64) {
        float m = smax[tid][0];
        #pragma unroll
        for (int x = 1; x < 16; x++) m = fmaxf(m, smax[tid][x]);
        scol[tid] = m * g_invncur[b * SPLIT + tid];
    }
    __syncthreads();
    if (tid == 0) {
        float s = 0.f;
        #pragma unroll
        for (int q = 0; q < 64; q++) s += scol[q];
        g_scores[b * 2048 + n] = s;
    }
}

// ---------------------------------------------------------------------------
// Kernel C: per batch, top-k over csi scores (k sequential argmax passes),
// then emit the tuple outputs flattened into ONE float32 buffer, in
// reference-return order:
//   elements [0,            B*(kact+1))   : indices cast to float32
//   elements [B*(kact+1), 2*B*(kact+1))   : weights (float32)
// ---------------------------------------------------------------------------
__global__ void topk_kernel(float* __restrict__ out, int csi, int kact, int B) {
    int b = blockIdx.x;
    int tid = threadIdx.x;
    __shared__ float s[2048];
    __shared__ float rv[256];
    __shared__ int   ri[256];
    __shared__ float topv[KTOP + 1];
    __shared__ int   topi[KTOP + 1];

    for (int i = tid; i < csi; i += 256) s[i] = g_scores[b * 2048 + i];
    __syncthreads();

    for (int t = 0; t < kact; t++) {
        float bv = -INFINITY;
        int bi = 0x7FFFFFFF;
        for (int i = tid; i < csi; i += 256) {
            float v = s[i];
            if (v > bv) { bv = v; bi = i; }
        }
        rv[tid] = bv; ri[tid] = bi;
        __syncthreads();
        for (int str = 128; str > 0; str >>= 1) {
            if (tid < str) {
                if (rv[tid + str] > rv[tid] ||
                    (rv[tid + str] == rv[tid] && ri[tid + str] < ri[tid])) {
                    rv[tid] = rv[tid + str];
                    ri[tid] = ri[tid + str];
                }
            }
            __syncthreads();
        }
        if (tid == 0) {
            topv[t] = rv[0];
            topi[t] = ri[0];
            s[ri[0]] = -INFINITY;
        }
        __syncthreads();
    }

    if (tid == 0) {
        int width = kact + 1;
        int woff = B * width;          // weights section start (in float elements)
        float mx = topv[0];            // top_k is sorted descending
        for (int j = 0; j < kact; j++) {
            out[b * width + j]        = (float)topi[j];
            out[woff + b * width + j] = topv[j] / (mx + 1e-8f);
        }
        out[b * width + kact]        = (float)csi;
        out[woff + b * width + kact] = 1.0f;
    }
}

// ---------------------------------------------------------------------------
extern "C" void kernel_launch(void* const* d_in, const int* in_sizes, int n_in,
                              void* d_out, int out_size) {
    const float* emb = (const float*)d_in[0];
    long long total = (long long)in_sizes[0];
    int n_avail = (int)(total / ((long long)BATCH * DMODEL * SPLIT));
    int csi = n_avail - 1;
    int kact = csi < KTOP ? csi : KTOP;

    dim3 gA(SPLIT, BATCH);
    curnorm_kernel<<<gA, 128>>>(emb, csi);

    dim3 gB(csi, BATCH);
    sim_kernel<<<gB, 256>>>(emb, csi);

    topk_kernel<<<BATCH, 256>>>((float*)d_out, csi, kact, BATCH);
}

// round 4
// speedup vs baseline: 1.0004x; 1.0004x over previous
#include <cuda_runtime.h>
#include <math.h>
#include <stdint.h>

// Problem constants (dataset-fixed): B=2, d_model=1024, SPLIT=64.
// n_avail derived from in_sizes[0] at launch.
#define BATCH   2
#define DMODEL  1024
#define SPLIT   64
#define KTOP    7

// Scratch (device globals; no allocation allowed)
__device__ float g_invncur[BATCH * SPLIT];      // inverse norms of current split rows
__device__ float g_scores[BATCH * 2048];        // scores[b][n]

// ---------------------------------------------------------------------------
// Kernel A: inverse L2 norms of the current split's 64 rows per batch.
// grid (SPLIT, BATCH), 128 threads.
// ---------------------------------------------------------------------------
__global__ void curnorm_kernel(const float* __restrict__ emb, int csi) {
    int q = blockIdx.x;
    int b = blockIdx.y;
    const float* row = emb + ((size_t)(b * (csi + 1) + csi) * SPLIT + q) * DMODEL;
    int tid = threadIdx.x;

    float ss = 0.f;
    // 1024 floats = 256 float4; 128 threads x 2
    #pragma unroll
    for (int it = 0; it < 2; it++) {
        float4 v = *(const float4*)(row + (tid + it * 128) * 4);
        ss += v.x * v.x + v.y * v.y + v.z * v.z + v.w * v.w;
    }
    // warp reduce
    #pragma unroll
    for (int o = 16; o > 0; o >>= 1)
        ss += __shfl_xor_sync(0xFFFFFFFF, ss, o);
    __shared__ float wred[4];
    if ((tid & 31) == 0) wred[tid >> 5] = ss;
    __syncthreads();
    if (tid == 0) {
        float t = wred[0] + wred[1] + wred[2] + wred[3];
        g_invncur[b * SPLIT + q] = 1.0f / fmaxf(sqrtf(t), 1e-12f);
    }
}

// ---------------------------------------------------------------------------
// Kernel B: per (b, n): 64x64x1024 dot matrix of cur x prev_n^T, fused
// prev-row norms, row-max over p, weighted sum over q -> scores[b][n].
// grid (csi, BATCH), 256 threads (16x16), 4x4 register tile, K-chunk 64.
// SMEM tiles stored transposed [k][row] with pad 68 to kill bank conflicts.
// ---------------------------------------------------------------------------
__global__ void __launch_bounds__(256) sim_kernel(const float* __restrict__ emb, int csi) {
    int n = blockIdx.x;
    int b = blockIdx.y;

    const float* cur  = emb + ((size_t)b * (csi + 1) + csi) * SPLIT * DMODEL;
    const float* prev = emb + ((size_t)b * (csi + 1) + n)   * SPLIT * DMODEL;

    __shared__ __align__(16) float As[64][68];   // As[k][q]  (cur, transposed)
    __shared__ __align__(16) float Bs[64][68];   // Bs[k][p]  (prev, transposed)

    int tid = threadIdx.x;
    int tx = tid & 15;          // p tile
    int ty = tid >> 4;          // q tile
    int prow  = tid & 63;       // sumsq row
    int kpart = tid >> 6;       // sumsq k-quarter

    float acc[4][4];
    #pragma unroll
    for (int i = 0; i < 4; i++)
        #pragma unroll
        for (int j = 0; j < 4; j++) acc[i][j] = 0.f;
    float ssq = 0.f;

    for (int kk = 0; kk < DMODEL; kk += 64) {
        // Load 64 rows x 64 cols of each operand, transposed into SMEM.
        #pragma unroll
        for (int it = 0; it < 4; it++) {
            int lin = tid + it * 256;   // 0..1023
            int c4  = lin & 15;         // float4 column index
            int row = lin >> 4;         // 0..63
            float4 va = *(const float4*)(cur  + (size_t)row * DMODEL + kk + c4 * 4);
            float4 vb = *(const float4*)(prev + (size_t)row * DMODEL + kk + c4 * 4);
            As[c4 * 4 + 0][row] = va.x; As[c4 * 4 + 1][row] = va.y;
            As[c4 * 4 + 2][row] = va.z; As[c4 * 4 + 3][row] = va.w;
            Bs[c4 * 4 + 0][row] = vb.x; Bs[c4 * 4 + 1][row] = vb.y;
            Bs[c4 * 4 + 2][row] = vb.z; Bs[c4 * 4 + 3][row] = vb.w;
        }
        __syncthreads();

        // Fused prev-row sumsq: thread covers (row = prow, k quarter = kpart).
        #pragma unroll
        for (int k2 = 0; k2 < 16; k2++) {
            float v = Bs[kpart * 16 + k2][prow];
            ssq += v * v;
        }

        // Main 4x4 outer-product accumulation.
        #pragma unroll
        for (int k = 0; k < 64; k++) {
            float4 a  = *(const float4*)&As[k][ty * 4];
            float4 b4 = *(const float4*)&Bs[k][tx * 4];
            acc[0][0] += a.x * b4.x; acc[0][1] += a.x * b4.y; acc[0][2] += a.x * b4.z; acc[0][3] += a.x * b4.w;
            acc[1][0] += a.y * b4.x; acc[1][1] += a.y * b4.y; acc[1][2] += a.y * b4.z; acc[1][3] += a.y * b4.w;
            acc[2][0] += a.z * b4.x; acc[2][1] += a.z * b4.y; acc[2][2] += a.z * b4.z; acc[2][3] += a.z * b4.w;
            acc[3][0] += a.w * b4.x; acc[3][1] += a.w * b4.y; acc[3][2] += a.w * b4.z; acc[3][3] += a.w * b4.w;
        }
        __syncthreads();
    }

    // Reduce prev sumsq -> inverse norms.
    __shared__ float sred[4][64];
    sred[kpart][prow] = ssq;
    __syncthreads();
    __shared__ float sinvp[64];
    if (tid < 64) {
        float t = sred[0][tid] + sred[1][tid] + sred[2][tid] + sred[3][tid];
        sinvp[tid] = 1.0f / fmaxf(sqrtf(t), 1e-12f);
    }
    __syncthreads();

    // Per-thread max over its 4 p's (after scaling by invp), then reduce over tx.
    __shared__ float smax[64][17];
    #pragma unroll
    for (int i = 0; i < 4; i++) {
        float m = -INFINITY;
        #pragma unroll
        for (int j = 0; j < 4; j++)
            m = fmaxf(m, acc[i][j] * sinvp[tx * 4 + j]);
        smax[ty * 4 + i][tx] = m;
    }
    __syncthreads();

    __shared__ float scol[64];
    if (tid < 64) {
        float m = smax[tid][0];
        #pragma unroll
        for (int x = 1; x < 16; x++) m = fmaxf(m, smax[tid][x]);
        scol[tid] = m * g_invncur[b * SPLIT + tid];
    }
    __syncthreads();
    if (tid == 0) {
        float s = 0.f;
        #pragma unroll
        for (int q = 0; q < 64; q++) s += scol[q];
        g_scores[b * 2048 + n] = s;
    }
}

// ---------------------------------------------------------------------------
// Kernel C: per batch, top-k over csi scores (k sequential argmax passes),
// then emit the tuple outputs flattened into ONE float32 buffer, in
// reference-return order:
//   elements [0,            B*(kact+1))   : indices cast to float32
//   elements [B*(kact+1), 2*B*(kact+1))   : weights (float32)
// ---------------------------------------------------------------------------
__global__ void topk_kernel(float* __restrict__ out, int csi, int kact, int B) {
    int b = blockIdx.x;
    int tid = threadIdx.x;
    __shared__ float s[2048];
    __shared__ float rv[256];
    __shared__ int   ri[256];
    __shared__ float topv[KTOP + 1];
    __shared__ int   topi[KTOP + 1];

    for (int i = tid; i < csi; i += 256) s[i] = g_scores[b * 2048 + i];
    __syncthreads();

    for (int t = 0; t < kact; t++) {
        float bv = -INFINITY;
        int bi = 0x7FFFFFFF;
        for (int i = tid; i < csi; i += 256) {
            float v = s[i];
            if (v > bv) { bv = v; bi = i; }
        }
        rv[tid] = bv; ri[tid] = bi;
        __syncthreads();
        for (int str = 128; str > 0; str >>= 1) {
            if (tid < str) {
                if (rv[tid + str] > rv[tid] ||
                    (rv[tid + str] == rv[tid] && ri[tid + str] < ri[tid])) {
                    rv[tid] = rv[tid + str];
                    ri[tid] = ri[tid + str];
                }
            }
            __syncthreads();
        }
        if (tid == 0) {
            topv[t] = rv[0];
            topi[t] = ri[0];
            s[ri[0]] = -INFINITY;
        }
        __syncthreads();
    }

    if (tid == 0) {
        int width = kact + 1;
        int woff = B * width;          // weights section start (in float elements)
        float mx = topv[0];            // top_k is sorted descending
        for (int j = 0; j < kact; j++) {
            out[b * width + j]        = (float)topi[j];
            out[woff + b * width + j] = topv[j] / (mx + 1e-8f);
        }
        out[b * width + kact]        = (float)csi;
        out[woff + b * width + kact] = 1.0f;
    }
}

// ---------------------------------------------------------------------------
extern "C" void kernel_launch(void* const* d_in, const int* in_sizes, int n_in,
                              void* d_out, int out_size) {
    const float* emb = (const float*)d_in[0];
    long long total = (long long)in_sizes[0];
    int n_avail = (int)(total / ((long long)BATCH * DMODEL * SPLIT));
    int csi = n_avail - 1;
    int kact = csi < KTOP ? csi : KTOP;

    dim3 gA(SPLIT, BATCH);
    curnorm_kernel<<<gA, 128>>>(emb, csi);

    dim3 gB(csi, BATCH);
    sim_kernel<<<gB, 256>>>(emb, csi);

    topk_kernel<<<BATCH, 256>>>((float*)d_out, csi, kact, BATCH);
}

// round 10
// speedup vs baseline: 2.7799x; 2.7789x over previous
#include <cuda_runtime.h>
#include <math.h>
#include <stdint.h>

#define BATCH   2
#define DMODEL  1024
#define SPLIT   64
#define KTOP    7

#define CHUNK   32
#define NCHUNK  (DMODEL / CHUNK)      // 32
#define APITCH  36                    // floats per smem row (conflict-free)
#define AROWS   256                   // 4 splits per CTA
#define BROWS   64
#define AFLOATS (AROWS * APITCH)      // 9216
#define BFLOATS (BROWS * APITCH)      // 2304
#define DYNF    (2 * (AFLOATS + BFLOATS))
#define DYNB    (DYNF * 4)            // 92160 bytes

// Scratch (device globals; no allocation allowed)
__device__ float g_invncur[BATCH * SPLIT];
__device__ float g_scores[BATCH * 2048];

__device__ __forceinline__ uint32_t smem_u32(const void* p) {
    uint32_t a;
    asm("{ .reg .u64 t; cvta.to.shared.u64 t, %1; cvt.u32.u64 %0, t; }"
        : "=r"(a) : "l"(p));
    return a;
}
__device__ __forceinline__ void cp16(uint32_t dst, const void* src) {
    asm volatile("cp.async.cg.shared.global [%0], [%1], 16;"
                 :: "r"(dst), "l"(src) : "memory");
}

// ---------------------------------------------------------------------------
// Kernel A: inverse L2 norms of the current split's 64 rows per batch.
// ---------------------------------------------------------------------------
__global__ void curnorm_kernel(const float* __restrict__ emb, int csi) {
    int q = blockIdx.x;
    int b = blockIdx.y;
    const float* row = emb + ((size_t)(b * (csi + 1) + csi) * SPLIT + q) * DMODEL;
    int tid = threadIdx.x;

    float ss = 0.f;
    #pragma unroll
    for (int it = 0; it < 2; it++) {
        float4 v = *(const float4*)(row + (tid + it * 128) * 4);
        ss += v.x * v.x + v.y * v.y + v.z * v.z + v.w * v.w;
    }
    #pragma unroll
    for (int o = 16; o > 0; o >>= 1)
        ss += __shfl_xor_sync(0xFFFFFFFF, ss, o);
    __shared__ float wred[4];
    if ((tid & 31) == 0) wred[tid >> 5] = ss;
    __syncthreads();
    if (tid == 0) {
        float t = wred[0] + wred[1] + wred[2] + wred[3];
        g_invncur[b * SPLIT + q] = 1.0f / fmaxf(sqrtf(t), 1e-12f);
    }
}

// ---------------------------------------------------------------------------
// Kernel B: tf32 mma.sync GEMM. Per CTA: batch b, splits 4x..4x+3.
//   A = prev rows [row0 .. row0+255]  (M = 256)
//   B = cur rows  [0 .. 63]           (N = 64)
//   D[p][q] = raw dot(prev_p, cur_q); normalize via fused fp32 norms; then
//   per-split per-col max over p, dot with g_invncur -> g_scores.
// 8 warps, warp tile 32x64, m16n8k8 tf32, cp.async double-buffered K-chunks.
// ---------------------------------------------------------------------------
__global__ void __launch_bounds__(256, 2)
sim_mma_kernel(const float* __restrict__ emb, int csi) {
    extern __shared__ float sm[];
    __shared__ float sinvp[256];
    __shared__ float wcolmax[8][64];
    __shared__ float partial[8];

    int tid = threadIdx.x;
    int w = tid >> 5, lane = tid & 31, g = lane >> 2, c = lane & 3;
    int b = blockIdx.y;
    int row0 = blockIdx.x * 256;
    int maxrow = csi * SPLIT - 1;

    const float* base = emb + (size_t)b * (csi + 1) * SPLIT * DMODEL;
    const float* curp = base + (size_t)csi * SPLIT * DMODEL;

    // A source row for this thread (clamped; clamped rows land in splits
    // >= csi which are never emitted)
    int arow = row0 + tid;
    if (arow > maxrow) arow = maxrow;
    const float* asrc = base + (size_t)arow * DMODEL;

    uint32_t sm_u = smem_u32(sm);

    float acc[2][8][4];
    #pragma unroll
    for (int i = 0; i < 2; i++)
        #pragma unroll
        for (int j = 0; j < 8; j++)
            #pragma unroll
            for (int x = 0; x < 4; x++) acc[i][j][x] = 0.f;
    float ssq = 0.f;

    auto load_chunk = [&](int it, int pbuf) {
        int kk = it * CHUNK;
        // A: 256 rows x 32 cols; thread = one row, 8 x 16B
        uint32_t adst = sm_u + (uint32_t)(pbuf * AFLOATS + tid * APITCH) * 4;
        #pragma unroll
        for (int j = 0; j < 8; j++)
            cp16(adst + j * 16, asrc + kk + j * 4);
        // B: 64 rows x 32 cols; 512 x 16B over 256 threads
        uint32_t bbase = sm_u + (uint32_t)(2 * AFLOATS + pbuf * BFLOATS) * 4;
        #pragma unroll
        for (int u = 0; u < 2; u++) {
            int idx = tid + u * 256;
            int n = idx >> 3, j = idx & 7;
            cp16(bbase + (uint32_t)(n * APITCH + j * 4) * 4,
                 curp + (size_t)n * DMODEL + kk + j * 4);
        }
        asm volatile("cp.async.commit_group;" ::: "memory");
    };

    load_chunk(0, 0);

    for (int it = 0; it < NCHUNK; it++) {
        if (it + 1 < NCHUNK) {
            load_chunk(it + 1, (it + 1) & 1);
            asm volatile("cp.async.wait_group 1;" ::: "memory");
        } else {
            asm volatile("cp.async.wait_group 0;" ::: "memory");
        }
        __syncthreads();

        const float* Ab = sm + (it & 1) * AFLOATS;
        const float* Bb = sm + 2 * AFLOATS + (it & 1) * BFLOATS;

        // fused prev-row sumsq (fp32, original values)
        #pragma unroll
        for (int j = 0; j < 8; j++) {
            float4 v = *(const float4*)&Ab[tid * APITCH + j * 4];
            ssq += v.x * v.x + v.y * v.y + v.z * v.z + v.w * v.w;
        }

        const float* Aw = Ab + (w * 32) * APITCH;
        #pragma unroll
        for (int k4 = 0; k4 < 4; k4++) {
            int k0 = k4 * 8;
            uint32_t a[2][4];
            #pragma unroll
            for (int i = 0; i < 2; i++) {
                int rb = 16 * i + g;
                a[i][0] = __float_as_uint(Aw[rb * APITCH + k0 + c]);
                a[i][1] = __float_as_uint(Aw[(rb + 8) * APITCH + k0 + c]);
                a[i][2] = __float_as_uint(Aw[rb * APITCH + k0 + c + 4]);
                a[i][3] = __float_as_uint(Aw[(rb + 8) * APITCH + k0 + c + 4]);
            }
            #pragma unroll
            for (int j = 0; j < 8; j++) {
                uint32_t b0 = __float_as_uint(Bb[(8 * j + g) * APITCH + k0 + c]);
                uint32_t b1 = __float_as_uint(Bb[(8 * j + g) * APITCH + k0 + c + 4]);
                #pragma unroll
                for (int i = 0; i < 2; i++) {
                    asm volatile(
                        "mma.sync.aligned.m16n8k8.row.col.f32.tf32.tf32.f32 "
                        "{%0,%1,%2,%3}, {%4,%5,%6,%7}, {%8,%9}, {%0,%1,%2,%3};"
                        : "+f"(acc[i][j][0]), "+f"(acc[i][j][1]),
                          "+f"(acc[i][j][2]), "+f"(acc[i][j][3])
                        : "r"(a[i][0]), "r"(a[i][1]), "r"(a[i][2]), "r"(a[i][3]),
                          "r"(b0), "r"(b1));
                }
            }
        }
        __syncthreads();
    }

    // prev-row inverse norms
    sinvp[tid] = 1.0f / fmaxf(sqrtf(ssq), 1e-12f);
    __syncthreads();

    // per-warp col maxima over its 32 rows (scaled by inv prev norm)
    #pragma unroll
    for (int j = 0; j < 8; j++) {
        #pragma unroll
        for (int cc = 0; cc < 2; cc++) {
            float m = -INFINITY;
            #pragma unroll
            for (int i = 0; i < 2; i++) {
                int r0 = w * 32 + 16 * i + g;
                m = fmaxf(m, acc[i][j][cc] * sinvp[r0]);
                m = fmaxf(m, acc[i][j][cc + 2] * sinvp[r0 + 8]);
            }
            m = fmaxf(m, __shfl_xor_sync(0xFFFFFFFF, m, 4));
            m = fmaxf(m, __shfl_xor_sync(0xFFFFFFFF, m, 8));
            m = fmaxf(m, __shfl_xor_sync(0xFFFFFFFF, m, 16));
            if (g == 0) wcolmax[w][8 * j + 2 * c + cc] = m;
        }
    }
    __syncthreads();

    // split scores: split s owns warps 2s, 2s+1 (rows 64s..64s+63)
    {
        int s = tid >> 6, q = tid & 63;
        float m = fmaxf(wcolmax[2 * s][q], wcolmax[2 * s + 1][q]);
        float val = m * g_invncur[b * SPLIT + q];
        #pragma unroll
        for (int o = 16; o > 0; o >>= 1)
            val += __shfl_xor_sync(0xFFFFFFFF, val, o);
        if (lane == 0) partial[w] = val;
    }
    __syncthreads();
    if (tid < 4) {
        int n_global = blockIdx.x * 4 + tid;
        if (n_global < csi)
            g_scores[b * 2048 + n_global] = partial[2 * tid] + partial[2 * tid + 1];
    }
}

// ---------------------------------------------------------------------------
// Kernel C: top-k + flat float32 output [indices | weights]
// ---------------------------------------------------------------------------
__global__ void topk_kernel(float* __restrict__ out, int csi, int kact, int B) {
    int b = blockIdx.x;
    int tid = threadIdx.x;
    __shared__ float s[2048];
    __shared__ float rv[256];
    __shared__ int   ri[256];
    __shared__ float topv[KTOP + 1];
    __shared__ int   topi[KTOP + 1];

    for (int i = tid; i < csi; i += 256) s[i] = g_scores[b * 2048 + i];
    __syncthreads();

    for (int t = 0; t < kact; t++) {
        float bv = -INFINITY;
        int bi = 0x7FFFFFFF;
        for (int i = tid; i < csi; i += 256) {
            float v = s[i];
            if (v > bv) { bv = v; bi = i; }
        }
        rv[tid] = bv; ri[tid] = bi;
        __syncthreads();
        for (int str = 128; str > 0; str >>= 1) {
            if (tid < str) {
                if (rv[tid + str] > rv[tid] ||
                    (rv[tid + str] == rv[tid] && ri[tid + str] < ri[tid])) {
                    rv[tid] = rv[tid + str];
                    ri[tid] = ri[tid + str];
                }
            }
            __syncthreads();
        }
        if (tid == 0) {
            topv[t] = rv[0];
            topi[t] = ri[0];
            s[ri[0]] = -INFINITY;
        }
        __syncthreads();
    }

    if (tid == 0) {
        int width = kact + 1;
        int woff = B * width;
        float mx = topv[0];
        for (int j = 0; j < kact; j++) {
            out[b * width + j]        = (float)topi[j];
            out[woff + b * width + j] = topv[j] / (mx + 1e-8f);
        }
        out[b * width + kact]        = (float)csi;
        out[woff + b * width + kact] = 1.0f;
    }
}

// ---------------------------------------------------------------------------
extern "C" void kernel_launch(void* const* d_in, const int* in_sizes, int n_in,
                              void* d_out, int out_size) {
    const float* emb = (const float*)d_in[0];
    long long total = (long long)in_sizes[0];
    int n_avail = (int)(total / ((long long)BATCH * DMODEL * SPLIT));
    int csi = n_avail - 1;
    int kact = csi < KTOP ? csi : KTOP;

    cudaFuncSetAttribute(sim_mma_kernel,
                         cudaFuncAttributeMaxDynamicSharedMemorySize, DYNB);

    dim3 gA(SPLIT, BATCH);
    curnorm_kernel<<<gA, 128>>>(emb, csi);

    int nb = (csi + 3) / 4;                 // 4 splits per CTA
    dim3 gB(nb, BATCH);
    sim_mma_kernel<<<gB, 256, DYNB>>>(emb, csi);

    topk_kernel<<<BATCH, 256>>>((float*)d_out, csi, kact, BATCH);
}